// round 8
// baseline (speedup 1.0000x reference)
#include <cuda_runtime.h>
#include <cuda_fp16.h>
#include <cstdint>

#define NA 8
#define SM_X 0            // 32768 B
#define SM_H 32768        // 65536 B
#define SMEM_TOTAL 98304

__device__ float g_esum[32768], g_nsum[32768], gv_e[32768], gv_n[32768];
__device__ uint2 w1e_hi_g[8192], w1e_lo_g[8192], w1n_hi_g[8192], w1n_lo_g[8192];
__device__ uint2 w2e_hi_g[8192], w2n_hi_g[8192];

__device__ __forceinline__ uint32_t pk_hi(float a, float b) {
    __half2 h = __floats2half2_rn(a, b);
    return *(uint32_t*)&h;
}
__device__ __forceinline__ uint32_t pk_lo(float a, float b) {
    return pk_hi(a - __half2float(__float2half_rn(a)),
                 b - __half2float(__float2half_rn(b)));
}
__device__ __forceinline__ void mma8(float* c, uint4 a, uint2 b) {
    asm volatile("mma.sync.aligned.m16n8k16.row.col.f32.f16.f16.f32 "
        "{%0,%1,%2,%3}, {%4,%5,%6,%7}, {%8,%9}, {%0,%1,%2,%3};"
        : "+f"(c[0]), "+f"(c[1]), "+f"(c[2]), "+f"(c[3])
        : "r"(a.x), "r"(a.y), "r"(a.z), "r"(a.w), "r"(b.x), "r"(b.y));
}

// ---------------- prep (single kernel) ----------------
__global__ void prep_all(const float* __restrict__ G,
                         const float* __restrict__ We2_g, const float* __restrict__ be2,
                         const float* __restrict__ Wn2_g, const float* __restrict__ bn2,
                         const float* __restrict__ We1, const float* __restrict__ Wn1,
                         const float* __restrict__ We2, const float* __restrict__ Wn2) {
    int tid = threadIdx.x;
    // gv + accumulator zero: one graph per block, threads<128
    if (tid < 128) {
        int g = blockIdx.x, c = tid;
        g_esum[g * 128 + c] = 0.f;
        g_nsum[g * 128 + c] = 0.f;
        float se = be2[c], sn = bn2[c];
        #pragma unroll 8
        for (int j = 0; j < 64; j++) {
            float gj = G[g * 64 + j];
            se += gj * We2_g[j * 128 + c];
            sn += gj * Wn2_g[j * 128 + c];
        }
        gv_e[g * 128 + c] = se;
        gv_n[g * 128 + c] = sn;
    }
    // weight fragment images: flat id, each thread <=1 entry of each family
    int i = blockIdx.x * 256 + tid;
    if (i < 8192) {
        int lane = i & 31, n8 = (i >> 5) & 31, ks = i >> 10;
        int k0 = ks * 16 + 2 * (lane & 3), n = n8 * 8 + (lane >> 2);
        float v0 = We1[k0 * 256 + n],       v1 = We1[(k0 + 1) * 256 + n];
        float v2 = We1[(k0 + 8) * 256 + n], v3 = We1[(k0 + 9) * 256 + n];
        w1e_hi_g[i] = make_uint2(pk_hi(v0, v1), pk_hi(v2, v3));
        w1e_lo_g[i] = make_uint2(pk_lo(v0, v1), pk_lo(v2, v3));
        v0 = Wn1[k0 * 256 + n];       v1 = Wn1[(k0 + 1) * 256 + n];
        v2 = Wn1[(k0 + 8) * 256 + n]; v3 = Wn1[(k0 + 9) * 256 + n];
        w1n_hi_g[i] = make_uint2(pk_hi(v0, v1), pk_hi(v2, v3));
        w1n_lo_g[i] = make_uint2(pk_lo(v0, v1), pk_lo(v2, v3));
    } else if (i < 16384) {
        int j = i - 8192;
        int lane = j & 31, n8 = (j >> 5) & 15, ks2 = j >> 9;
        int k0 = ks2 * 16 + 2 * (lane & 3), n = n8 * 8 + (lane >> 2);
        float v0 = We2[k0 * 128 + n],       v1 = We2[(k0 + 1) * 128 + n];
        float v2 = We2[(k0 + 8) * 128 + n], v3 = We2[(k0 + 9) * 128 + n];
        w2e_hi_g[j] = make_uint2(pk_hi(v0, v1), pk_hi(v2, v3));
        v0 = Wn2[k0 * 128 + n];       v1 = Wn2[(k0 + 1) * 128 + n];
        v2 = Wn2[(k0 + 8) * 128 + n]; v3 = Wn2[(k0 + 9) * 128 + n];
        w2n_hi_g[j] = make_uint2(pk_hi(v0, v1), pk_hi(v2, v3));
    }
}

// ---------------- main: tile 128x128, 512 threads, warp grid 2m x 8n ----------------
__device__ __forceinline__ void do_tile(char* sm, const float* __restrict__ X,
        const uint2* __restrict__ w1h, const uint2* __restrict__ w1l,
        const uint2* __restrict__ w2h, const float* __restrict__ b1,
        const float* __restrict__ gv0, const float* __restrict__ gv1,
        float* __restrict__ gs0, float* __restrict__ gs1) {
    const int tid = threadIdx.x, w = tid >> 5, lane = tid & 31;
    const int mg = w >> 3, ng = w & 7;        // 2 x 8 warp grid
    const int mb = mg * 4;                    // m-tile base (4 of 8)
    uint32_t* Xs = (uint32_t*)(sm + SM_X);
    uint32_t* Hs = (uint32_t*)(sm + SM_H);

    // stage X [128,128] f32 -> fp16 plane-interleaved A-fragments
    const float4* Xg = (const float4*)X;
    #pragma unroll
    for (int i = 0; i < 8; i++) {
        int idx = tid + i * 512;
        int row = idx >> 5, c4 = (idx & 31) << 2;
        float4 v = Xg[idx];
        int f = ((c4 >> 4) << 3) + (row >> 4);
        int l = ((row & 7) << 2) + ((c4 >> 1) & 3);
        int p = ((row >> 3) & 1) + (((c4 >> 3) & 1) << 1);
        Xs[(f * 32 + l) * 4 + p]     = pk_hi(v.x, v.y);
        Xs[(f * 32 + l + 1) * 4 + p] = pk_hi(v.z, v.w);
    }
    __syncthreads();

    // GEMM1: warp owns 4 rt x 4 n8, W1 hi+lo
    float C[4][4][4];
    #pragma unroll
    for (int rt = 0; rt < 4; rt++)
        #pragma unroll
        for (int n = 0; n < 4; n++)
            #pragma unroll
            for (int q = 0; q < 4; q++) C[rt][n][q] = 0.f;
    const int nb = ng * 4;
    #pragma unroll 2
    for (int ks = 0; ks < 8; ks++) {
        uint2 BH[4], BL[4];
        #pragma unroll
        for (int n = 0; n < 4; n++) {
            BH[n] = __ldg(&w1h[(ks * 32 + nb + n) * 32 + lane]);
            BL[n] = __ldg(&w1l[(ks * 32 + nb + n) * 32 + lane]);
        }
        #pragma unroll
        for (int rt = 0; rt < 4; rt++) {
            uint4 a = *(const uint4*)(Xs + ((ks * 8 + mb + rt) * 32 + lane) * 4);
            #pragma unroll
            for (int n = 0; n < 4; n++) {
                mma8(C[rt][n], a, BH[n]);
                mma8(C[rt][n], a, BL[n]);
            }
        }
    }

    // epilogue1: bias+relu -> H fragments
    #pragma unroll
    for (int n = 0; n < 4; n++) {
        int c = (nb + n) * 8 + 2 * (lane & 3);
        float2 bb = *(const float2*)(b1 + c);
        int ks2 = (nb + n) >> 1, p = ((nb + n) & 1) * 2;
        #pragma unroll
        for (int rt = 0; rt < 4; rt++) {
            uint32_t u0 = pk_hi(fmaxf(C[rt][n][0] + bb.x, 0.f),
                                fmaxf(C[rt][n][1] + bb.y, 0.f));
            uint32_t u1 = pk_hi(fmaxf(C[rt][n][2] + bb.x, 0.f),
                                fmaxf(C[rt][n][3] + bb.y, 0.f));
            *(uint2*)(Hs + ((ks2 * 8 + mb + rt) * 32 + lane) * 4 + p) = make_uint2(u0, u1);
        }
    }
    __syncthreads();

    // GEMM2: warp owns 4 rt x 2 n8, W2 hi only
    float C2[4][2][4];
    #pragma unroll
    for (int rt = 0; rt < 4; rt++)
        #pragma unroll
        for (int n = 0; n < 2; n++)
            #pragma unroll
            for (int q = 0; q < 4; q++) C2[rt][n][q] = 0.f;
    const int nb2 = ng * 2;
    #pragma unroll 2
    for (int ks2 = 0; ks2 < 16; ks2++) {
        uint2 B0 = __ldg(&w2h[(ks2 * 16 + nb2) * 32 + lane]);
        uint2 B1 = __ldg(&w2h[(ks2 * 16 + nb2 + 1) * 32 + lane]);
        #pragma unroll
        for (int rt = 0; rt < 4; rt++) {
            uint4 a = *(const uint4*)(Hs + ((ks2 * 8 + mb + rt) * 32 + lane) * 4);
            mma8(C2[rt][0], a, B0);
            mma8(C2[rt][1], a, B1);
        }
    }

    // epilogue2: +gv, relu, column sums over this warp's 64-row group
    const float* gvp = mg ? gv1 : gv0;
    float* gsp = mg ? gs1 : gs0;
    #pragma unroll
    for (int n = 0; n < 2; n++) {
        int c = (nb2 + n) * 8 + 2 * (lane & 3);
        float2 gq = *(const float2*)(gvp + c);
        float s0 = 0.f, s1 = 0.f;
        #pragma unroll
        for (int rt = 0; rt < 4; rt++) {
            s0 += fmaxf(C2[rt][n][0] + gq.x, 0.f) + fmaxf(C2[rt][n][2] + gq.x, 0.f);
            s1 += fmaxf(C2[rt][n][1] + gq.y, 0.f) + fmaxf(C2[rt][n][3] + gq.y, 0.f);
        }
        #pragma unroll
        for (int d = 4; d < 32; d <<= 1) {
            s0 += __shfl_xor_sync(0xFFFFFFFF, s0, d);
            s1 += __shfl_xor_sync(0xFFFFFFFF, s1, d);
        }
        if (lane < 4) {
            atomicAdd(gsp + c, s0);
            atomicAdd(gsp + c + 1, s1);
        }
    }
    __syncthreads();
}

__global__ __launch_bounds__(512, 1)
void gnn_main(const float* __restrict__ edges, const float* __restrict__ nodes,
              const float* __restrict__ be1, const float* __restrict__ bn1) {
    extern __shared__ char sm[];
    for (int t = blockIdx.x; t < 2048; t += 148) {
        int g = t >> 3;
        do_tile(sm, edges + (size_t)t * 16384, w1e_hi_g, w1e_lo_g, w2e_hi_g,
                be1, gv_e + g * 128, gv_e + g * 128, g_esum + g * 128, g_esum + g * 128);
    }
    for (int t = blockIdx.x; t < 128; t += 148) {
        int g0 = t * 2;
        do_tile(sm, nodes + (size_t)t * 16384, w1n_hi_g, w1n_lo_g, w2n_hi_g,
                bn1, gv_n + g0 * 128, gv_n + g0 * 128 + 128,
                g_nsum + g0 * 128, g_nsum + g0 * 128 + 128);
    }
}

// ---------------- final: 16 blocks x 512 threads, 16 graphs/block ----------------
__global__ __launch_bounds__(512)
void final_k(const float* __restrict__ G, const float* __restrict__ A,
             const float* __restrict__ Wgn, const float* __restrict__ Wge,
             const float* __restrict__ Wgg, const float* __restrict__ bg,
             const float* __restrict__ Wh, const float* __restrict__ bh,
             const float* __restrict__ Wo, const float* __restrict__ bo,
             float* __restrict__ out) {
    __shared__ float navg[16 * 129], eavg[16 * 129], gl[16 * 66], sa[16 * 137], red[16];
    const int tid = threadIdx.x, gbase = blockIdx.x * 16;
    for (int i = tid; i < 16 * 128; i += 512) {
        int g = i >> 7, j = i & 127;
        navg[g * 129 + j] = g_nsum[(gbase + g) * 128 + j] * (1.f / 64.f);
        eavg[g * 129 + j] = g_esum[(gbase + g) * 128 + j] * (1.f / 1024.f);
    }
    for (int i = tid; i < 16 * 64; i += 512) {
        int g = i >> 6, j = i & 63;
        gl[g * 66 + j] = G[(gbase + g) * 64 + j];
    }
    if (tid < 16) red[tid] = 0.f;
    __syncthreads();
    {   // state_value: thread = (c, q); 4 graphs per thread
        int c = tid & 127, q = tid >> 7;
        float s[4] = {0.f, 0.f, 0.f, 0.f};
        for (int j = 0; j < 128; j++) {
            float wn = __ldg(Wgn + j * 128 + c), we = __ldg(Wge + j * 128 + c);
            #pragma unroll
            for (int i = 0; i < 4; i++) {
                int g = q + 4 * i;
                s[i] += navg[g * 129 + j] * wn + eavg[g * 129 + j] * we;
            }
        }
        for (int j = 0; j < 64; j++) {
            float wg = __ldg(Wgg + j * 128 + c);
            #pragma unroll
            for (int i = 0; i < 4; i++) s[i] += gl[(q + 4 * i) * 66 + j] * wg;
        }
        float bgc = bg[c];
        #pragma unroll
        for (int i = 0; i < 4; i++) sa[(q + 4 * i) * 137 + c] = s[i] + bgc;
    }
    for (int i = tid; i < 16 * NA; i += 512) {
        int g = i >> 3, j = i & 7;
        sa[g * 137 + 128 + j] = A[(gbase + g) * NA + j];
    }
    __syncthreads();
    {   // hidden + output: thread = (o, q); 8 graphs per thread
        int o = tid & 255, q = tid >> 8;
        float h[8];
        #pragma unroll
        for (int i = 0; i < 8; i++) h[i] = bh[o];
        for (int j = 0; j < 136; j++) {
            float wv = __ldg(Wh + j * 256 + o);
            #pragma unroll
            for (int i = 0; i < 8; i++) h[i] += sa[(q + 2 * i) * 137 + j] * wv;
        }
        float wo = Wo[o];
        #pragma unroll
        for (int i = 0; i < 8; i++) {
            float v = fmaxf(h[i], 0.f) * wo;
            #pragma unroll
            for (int d = 1; d < 32; d <<= 1) v += __shfl_xor_sync(0xFFFFFFFF, v, d);
            if ((tid & 31) == 0) atomicAdd(&red[q + 2 * i], v);
        }
    }
    __syncthreads();
    if (tid < 16) out[gbase + tid] = red[tid] + bo[0];
}

// ---------------- launch ----------------
extern "C" void kernel_launch(void* const* d_in, const int* in_sizes, int n_in,
                              void* d_out, int out_size) {
    (void)in_sizes; (void)n_in; (void)out_size;
    const float* nodes = (const float*)d_in[0];
    const float* edges = (const float*)d_in[1];
    const float* G     = (const float*)d_in[2];
    const float* a     = (const float*)d_in[5];
    const float* We1   = (const float*)d_in[6];
    const float* be1   = (const float*)d_in[7];
    const float* Wn1   = (const float*)d_in[8];
    const float* bn1   = (const float*)d_in[9];
    const float* We2_e = (const float*)d_in[10];
    const float* We2_g = (const float*)d_in[11];
    const float* be2   = (const float*)d_in[12];
    const float* Wn2_n = (const float*)d_in[13];
    const float* Wn2_g = (const float*)d_in[14];
    const float* bn2   = (const float*)d_in[15];
    const float* Wg_n  = (const float*)d_in[16];
    const float* Wg_e  = (const float*)d_in[17];
    const float* Wg_g  = (const float*)d_in[18];
    const float* bg    = (const float*)d_in[19];
    const float* Wh    = (const float*)d_in[20];
    const float* bh    = (const float*)d_in[21];
    const float* Wo    = (const float*)d_in[22];
    const float* bo    = (const float*)d_in[23];
    float* out = (float*)d_out;

    cudaFuncSetAttribute(gnn_main, cudaFuncAttributeMaxDynamicSharedMemorySize, SMEM_TOTAL);
    prep_all<<<256, 256>>>(G, We2_g, be2, Wn2_g, bn2, We1, Wn1, We2_e, Wn2_n);
    gnn_main<<<148, 512, SMEM_TOTAL>>>(edges, nodes, be1, bn1);
    final_k<<<16, 512>>>(G, a, Wg_n, Wg_e, Wg_g, bg, Wh, bh, Wo, bo, out);
}

// round 9
// speedup vs baseline: 1.1621x; 1.1621x over previous
#include <cuda_runtime.h>
#include <cuda_fp16.h>
#include <cstdint>

#define NA 8
#define SM_W1 0           // 65536 B : W1 hi fragment image
#define SM_W2 65536       // 65536 B : W2 hi fragment image
#define SM_X  131072      // 32768 B
#define SM_H  163840      // 65536 B
#define SM_B1 229376      // 1024 B
#define SMEM_TOTAL 230400

__device__ float g_esum[32768], g_nsum[32768], gv_e[32768], gv_n[32768];
__device__ uint2 w1e_g[8192], w1n_g[8192], w2e_g[8192], w2n_g[8192];

__device__ __forceinline__ uint32_t pk_hi(float a, float b) {
    __half2 h = __floats2half2_rn(a, b);
    return *(uint32_t*)&h;
}
__device__ __forceinline__ void mma8(float* c, uint4 a, uint2 b) {
    asm volatile("mma.sync.aligned.m16n8k16.row.col.f32.f16.f16.f32 "
        "{%0,%1,%2,%3}, {%4,%5,%6,%7}, {%8,%9}, {%0,%1,%2,%3};"
        : "+f"(c[0]), "+f"(c[1]), "+f"(c[2]), "+f"(c[3])
        : "r"(a.x), "r"(a.y), "r"(a.z), "r"(a.w), "r"(b.x), "r"(b.y));
}

// ---------------- prep ----------------
__global__ void prep_all(const float* __restrict__ G,
                         const float* __restrict__ We2_g, const float* __restrict__ be2,
                         const float* __restrict__ Wn2_g, const float* __restrict__ bn2,
                         const float* __restrict__ We1, const float* __restrict__ Wn1,
                         const float* __restrict__ We2, const float* __restrict__ Wn2) {
    int tid = threadIdx.x;
    if (tid < 128) {
        int g = blockIdx.x, c = tid;
        g_esum[g * 128 + c] = 0.f;
        g_nsum[g * 128 + c] = 0.f;
        float se = be2[c], sn = bn2[c];
        #pragma unroll 8
        for (int j = 0; j < 64; j++) {
            float gj = G[g * 64 + j];
            se += gj * We2_g[j * 128 + c];
            sn += gj * Wn2_g[j * 128 + c];
        }
        gv_e[g * 128 + c] = se;
        gv_n[g * 128 + c] = sn;
    }
    int i = blockIdx.x * 256 + tid;
    if (i < 8192) {   // W1 image: j = (ks*32 + n8)*32 + lane
        int lane = i & 31, n8 = (i >> 5) & 31, ks = i >> 10;
        int k0 = ks * 16 + 2 * (lane & 3), n = n8 * 8 + (lane >> 2);
        w1e_g[i] = make_uint2(pk_hi(We1[k0 * 256 + n], We1[(k0 + 1) * 256 + n]),
                              pk_hi(We1[(k0 + 8) * 256 + n], We1[(k0 + 9) * 256 + n]));
        w1n_g[i] = make_uint2(pk_hi(Wn1[k0 * 256 + n], Wn1[(k0 + 1) * 256 + n]),
                              pk_hi(Wn1[(k0 + 8) * 256 + n], Wn1[(k0 + 9) * 256 + n]));
    } else if (i < 16384) {   // W2 image: j = (ks2*16 + n8)*32 + lane
        int j = i - 8192;
        int lane = j & 31, n8 = (j >> 5) & 15, ks2 = j >> 9;
        int k0 = ks2 * 16 + 2 * (lane & 3), n = n8 * 8 + (lane >> 2);
        w2e_g[j] = make_uint2(pk_hi(We2[k0 * 128 + n], We2[(k0 + 1) * 128 + n]),
                              pk_hi(We2[(k0 + 8) * 128 + n], We2[(k0 + 9) * 128 + n]));
        w2n_g[j] = make_uint2(pk_hi(Wn2[k0 * 128 + n], Wn2[(k0 + 1) * 128 + n]),
                              pk_hi(Wn2[(k0 + 8) * 128 + n], Wn2[(k0 + 9) * 128 + n]));
    }
}

// ---------------- main ----------------
__device__ __forceinline__ void load_w(char* sm, const uint2* __restrict__ w1,
                                       const uint2* __restrict__ w2,
                                       const float* __restrict__ b1) {
    int tid = threadIdx.x;
    const uint4* s1 = (const uint4*)w1;
    const uint4* s2 = (const uint4*)w2;
    uint4* d1 = (uint4*)(sm + SM_W1);
    uint4* d2 = (uint4*)(sm + SM_W2);
    #pragma unroll
    for (int i = 0; i < 8; i++) {
        d1[tid + i * 512] = s1[tid + i * 512];
        d2[tid + i * 512] = s2[tid + i * 512];
    }
    if (tid < 256) ((float*)(sm + SM_B1))[tid] = b1[tid];
    __syncthreads();
}

// tile = 128 rows x 128 cols, 512 threads, warp grid 4m x 4n
__device__ __forceinline__ void do_tile(char* sm, const float* __restrict__ X,
        const float* __restrict__ gv0, const float* __restrict__ gv1,
        float* __restrict__ gs0, float* __restrict__ gs1) {
    const int tid = threadIdx.x, w = tid >> 5, lane = tid & 31;
    const int mg = w & 3, ng = w >> 2;     // 4 x 4 warp grid
    const int mb = mg * 2;                 // 2 m-tiles per warp
    uint32_t* Xs = (uint32_t*)(sm + SM_X);
    uint32_t* Hs = (uint32_t*)(sm + SM_H);
    const uint2* W1 = (const uint2*)(sm + SM_W1);
    const uint2* W2 = (const uint2*)(sm + SM_W2);
    const float* b1s = (const float*)(sm + SM_B1);

    // stage X [128,128] f32 -> fp16 plane-interleaved A-fragments
    const float4* Xg = (const float4*)X;
    #pragma unroll
    for (int i = 0; i < 8; i++) {
        int idx = tid + i * 512;
        int row = idx >> 5, c4 = (idx & 31) << 2;
        float4 v = Xg[idx];
        int f = ((c4 >> 4) << 3) + (row >> 4);
        int l = ((row & 7) << 2) + ((c4 >> 1) & 3);
        int p = ((row >> 3) & 1) + (((c4 >> 3) & 1) << 1);
        Xs[(f * 32 + l) * 4 + p]     = pk_hi(v.x, v.y);
        Xs[(f * 32 + l + 1) * 4 + p] = pk_hi(v.z, v.w);
    }
    __syncthreads();

    // GEMM1: warp = 2 rt x 8 n8, all from SMEM
    float C[2][8][4];
    #pragma unroll
    for (int rt = 0; rt < 2; rt++)
        #pragma unroll
        for (int n = 0; n < 8; n++)
            #pragma unroll
            for (int q = 0; q < 4; q++) C[rt][n][q] = 0.f;
    const int nb = ng * 8;
    #pragma unroll 1
    for (int ks = 0; ks < 8; ks++) {
        uint4 a0 = *(const uint4*)(Xs + ((ks * 8 + mb) * 32 + lane) * 4);
        uint4 a1 = *(const uint4*)(Xs + ((ks * 8 + mb + 1) * 32 + lane) * 4);
        #pragma unroll
        for (int n = 0; n < 8; n++) {
            uint2 b = W1[(ks * 32 + nb + n) * 32 + lane];
            mma8(C[0][n], a0, b);
            mma8(C[1][n], a1, b);
        }
    }

    // epilogue1: bias+relu -> H fragments (warp-exclusive slices)
    #pragma unroll
    for (int n = 0; n < 8; n++) {
        int c = (nb + n) * 8 + 2 * (lane & 3);
        float2 bb = *(const float2*)(b1s + c);
        int ks2 = (nb + n) >> 1, p = ((nb + n) & 1) * 2;
        #pragma unroll
        for (int rt = 0; rt < 2; rt++) {
            uint32_t u0 = pk_hi(fmaxf(C[rt][n][0] + bb.x, 0.f),
                                fmaxf(C[rt][n][1] + bb.y, 0.f));
            uint32_t u1 = pk_hi(fmaxf(C[rt][n][2] + bb.x, 0.f),
                                fmaxf(C[rt][n][3] + bb.y, 0.f));
            *(uint2*)(Hs + ((ks2 * 8 + mb + rt) * 32 + lane) * 4 + p) = make_uint2(u0, u1);
        }
    }
    __syncthreads();

    // GEMM2: warp = 2 rt x 4 n8, all from SMEM
    float C2[2][4][4];
    #pragma unroll
    for (int rt = 0; rt < 2; rt++)
        #pragma unroll
        for (int n = 0; n < 4; n++)
            #pragma unroll
            for (int q = 0; q < 4; q++) C2[rt][n][q] = 0.f;
    const int nb2 = ng * 4;
    #pragma unroll 1
    for (int ks2 = 0; ks2 < 16; ks2++) {
        uint4 a0 = *(const uint4*)(Hs + ((ks2 * 8 + mb) * 32 + lane) * 4);
        uint4 a1 = *(const uint4*)(Hs + ((ks2 * 8 + mb + 1) * 32 + lane) * 4);
        #pragma unroll
        for (int n = 0; n < 4; n++) {
            uint2 b = W2[(ks2 * 16 + nb2 + n) * 32 + lane];
            mma8(C2[0][n], a0, b);
            mma8(C2[1][n], a1, b);
        }
    }

    // epilogue2: +gv, relu, column sums (warp's rows 32mg..32mg+31)
    const float* gvp = (mg >= 2) ? gv1 : gv0;
    float* gsp = (mg >= 2) ? gs1 : gs0;
    #pragma unroll
    for (int n = 0; n < 4; n++) {
        int c = (nb2 + n) * 8 + 2 * (lane & 3);
        float2 gq = *(const float2*)(gvp + c);
        float s0 = 0.f, s1 = 0.f;
        #pragma unroll
        for (int rt = 0; rt < 2; rt++) {
            s0 += fmaxf(C2[rt][n][0] + gq.x, 0.f) + fmaxf(C2[rt][n][2] + gq.x, 0.f);
            s1 += fmaxf(C2[rt][n][1] + gq.y, 0.f) + fmaxf(C2[rt][n][3] + gq.y, 0.f);
        }
        #pragma unroll
        for (int d = 4; d < 32; d <<= 1) {
            s0 += __shfl_xor_sync(0xFFFFFFFF, s0, d);
            s1 += __shfl_xor_sync(0xFFFFFFFF, s1, d);
        }
        if (lane < 4) {
            atomicAdd(gsp + c, s0);
            atomicAdd(gsp + c + 1, s1);
        }
    }
    __syncthreads();
}

__global__ __launch_bounds__(512, 1)
void gnn_main(const float* __restrict__ edges, const float* __restrict__ nodes,
              const float* __restrict__ be1, const float* __restrict__ bn1) {
    extern __shared__ char sm[];
    load_w(sm, w1e_g, w2e_g, be1);
    for (int t = blockIdx.x; t < 2048; t += 148) {
        int g = t >> 3;
        do_tile(sm, edges + (size_t)t * 16384,
                gv_e + g * 128, gv_e + g * 128, g_esum + g * 128, g_esum + g * 128);
    }
    __syncthreads();
    load_w(sm, w1n_g, w2n_g, bn1);
    for (int t = blockIdx.x; t < 128; t += 148) {
        int g0 = t * 2;
        do_tile(sm, nodes + (size_t)t * 16384,
                gv_n + g0 * 128, gv_n + g0 * 128 + 128,
                g_nsum + g0 * 128, g_nsum + g0 * 128 + 128);
    }
}

// ---------------- final: 16 blocks x 512 threads, 16 graphs/block ----------------
__global__ __launch_bounds__(512)
void final_k(const float* __restrict__ G, const float* __restrict__ A,
             const float* __restrict__ Wgn, const float* __restrict__ Wge,
             const float* __restrict__ Wgg, const float* __restrict__ bg,
             const float* __restrict__ Wh, const float* __restrict__ bh,
             const float* __restrict__ Wo, const float* __restrict__ bo,
             float* __restrict__ out) {
    __shared__ float navg[16 * 129], eavg[16 * 129], gl[16 * 66], sa[16 * 137], red[16];
    const int tid = threadIdx.x, gbase = blockIdx.x * 16;
    for (int i = tid; i < 16 * 128; i += 512) {
        int g = i >> 7, j = i & 127;
        navg[g * 129 + j] = g_nsum[(gbase + g) * 128 + j] * (1.f / 64.f);
        eavg[g * 129 + j] = g_esum[(gbase + g) * 128 + j] * (1.f / 1024.f);
    }
    for (int i = tid; i < 16 * 64; i += 512) {
        int g = i >> 6, j = i & 63;
        gl[g * 66 + j] = G[(gbase + g) * 64 + j];
    }
    if (tid < 16) red[tid] = 0.f;
    __syncthreads();
    {
        int c = tid & 127, q = tid >> 7;
        float s[4] = {0.f, 0.f, 0.f, 0.f};
        for (int j = 0; j < 128; j++) {
            float wn = __ldg(Wgn + j * 128 + c), we = __ldg(Wge + j * 128 + c);
            #pragma unroll
            for (int i = 0; i < 4; i++) {
                int g = q + 4 * i;
                s[i] += navg[g * 129 + j] * wn + eavg[g * 129 + j] * we;
            }
        }
        for (int j = 0; j < 64; j++) {
            float wg = __ldg(Wgg + j * 128 + c);
            #pragma unroll
            for (int i = 0; i < 4; i++) s[i] += gl[(q + 4 * i) * 66 + j] * wg;
        }
        float bgc = bg[c];
        #pragma unroll
        for (int i = 0; i < 4; i++) sa[(q + 4 * i) * 137 + c] = s[i] + bgc;
    }
    for (int i = tid; i < 16 * NA; i += 512) {
        int g = i >> 3, j = i & 7;
        sa[g * 137 + 128 + j] = A[(gbase + g) * NA + j];
    }
    __syncthreads();
    {
        int o = tid & 255, q = tid >> 8;
        float h[8];
        #pragma unroll
        for (int i = 0; i < 8; i++) h[i] = bh[o];
        for (int j = 0; j < 136; j++) {
            float wv = __ldg(Wh + j * 256 + o);
            #pragma unroll
            for (int i = 0; i < 8; i++) h[i] += sa[(q + 2 * i) * 137 + j] * wv;
        }
        float wo = Wo[o];
        #pragma unroll
        for (int i = 0; i < 8; i++) {
            float v = fmaxf(h[i], 0.f) * wo;
            #pragma unroll
            for (int d = 1; d < 32; d <<= 1) v += __shfl_xor_sync(0xFFFFFFFF, v, d);
            if ((tid & 31) == 0) atomicAdd(&red[q + 2 * i], v);
        }
    }
    __syncthreads();
    if (tid < 16) out[gbase + tid] = red[tid] + bo[0];
}

// ---------------- launch ----------------
extern "C" void kernel_launch(void* const* d_in, const int* in_sizes, int n_in,
                              void* d_out, int out_size) {
    (void)in_sizes; (void)n_in; (void)out_size;
    const float* nodes = (const float*)d_in[0];
    const float* edges = (const float*)d_in[1];
    const float* G     = (const float*)d_in[2];
    const float* a     = (const float*)d_in[5];
    const float* We1   = (const float*)d_in[6];
    const float* be1   = (const float*)d_in[7];
    const float* Wn1   = (const float*)d_in[8];
    const float* bn1   = (const float*)d_in[9];
    const float* We2_e = (const float*)d_in[10];
    const float* We2_g = (const float*)d_in[11];
    const float* be2   = (const float*)d_in[12];
    const float* Wn2_n = (const float*)d_in[13];
    const float* Wn2_g = (const float*)d_in[14];
    const float* bn2   = (const float*)d_in[15];
    const float* Wg_n  = (const float*)d_in[16];
    const float* Wg_e  = (const float*)d_in[17];
    const float* Wg_g  = (const float*)d_in[18];
    const float* bg    = (const float*)d_in[19];
    const float* Wh    = (const float*)d_in[20];
    const float* bh    = (const float*)d_in[21];
    const float* Wo    = (const float*)d_in[22];
    const float* bo    = (const float*)d_in[23];
    float* out = (float*)d_out;

    cudaFuncSetAttribute(gnn_main, cudaFuncAttributeMaxDynamicSharedMemorySize, SMEM_TOTAL);
    prep_all<<<256, 256>>>(G, We2_g, be2, Wn2_g, bn2, We1, Wn1, We2_e, Wn2_n);
    gnn_main<<<148, 512, SMEM_TOTAL>>>(edges, nodes, be1, bn1);
    final_k<<<16, 512>>>(G, a, Wg_n, Wg_e, Wg_g, bg, Wh, bh, Wo, bo, out);
}

// round 10
// speedup vs baseline: 1.1942x; 1.0276x over previous
#include <cuda_runtime.h>
#include <cuda_fp16.h>
#include <cstdint>

#define NA 8
#define SM_W1 0           // 65536 B : W1 hi fragment image
#define SM_W2 65536       // 65536 B : W2 hi fragment image
#define SM_X  131072      // 32768 B
#define SM_H  163840      // 65536 B
#define SM_B1 229376      // 1024 B
#define SMEM_TOTAL 230400

__device__ float g_esum[32768], g_nsum[32768], gv_e[32768], gv_n[32768];
__device__ uint2 w1e_g[8192], w1n_g[8192], w2e_g[8192], w2n_g[8192];

__device__ __forceinline__ uint32_t pk_hi(float a, float b) {
    __half2 h = __floats2half2_rn(a, b);
    return *(uint32_t*)&h;
}
__device__ __forceinline__ void mma8(float* c, uint4 a, uint2 b) {
    asm volatile("mma.sync.aligned.m16n8k16.row.col.f32.f16.f16.f32 "
        "{%0,%1,%2,%3}, {%4,%5,%6,%7}, {%8,%9}, {%0,%1,%2,%3};"
        : "+f"(c[0]), "+f"(c[1]), "+f"(c[2]), "+f"(c[3])
        : "r"(a.x), "r"(a.y), "r"(a.z), "r"(a.w), "r"(b.x), "r"(b.y));
}

// ---------------- prep ----------------
__global__ void prep_all(const float* __restrict__ G,
                         const float* __restrict__ We2_g, const float* __restrict__ be2,
                         const float* __restrict__ Wn2_g, const float* __restrict__ bn2,
                         const float* __restrict__ We1, const float* __restrict__ Wn1,
                         const float* __restrict__ We2, const float* __restrict__ Wn2) {
    int tid = threadIdx.x;
    if (tid < 128) {
        int g = blockIdx.x, c = tid;
        g_esum[g * 128 + c] = 0.f;
        g_nsum[g * 128 + c] = 0.f;
        float se = be2[c], sn = bn2[c];
        #pragma unroll 8
        for (int j = 0; j < 64; j++) {
            float gj = G[g * 64 + j];
            se += gj * We2_g[j * 128 + c];
            sn += gj * Wn2_g[j * 128 + c];
        }
        gv_e[g * 128 + c] = se;
        gv_n[g * 128 + c] = sn;
    }
    int i = blockIdx.x * 256 + tid;
    if (i < 8192) {   // W1 image: (ks*32 + n8)*32 + lane
        int lane = i & 31, n8 = (i >> 5) & 31, ks = i >> 10;
        int k0 = ks * 16 + 2 * (lane & 3), n = n8 * 8 + (lane >> 2);
        w1e_g[i] = make_uint2(pk_hi(We1[k0 * 256 + n], We1[(k0 + 1) * 256 + n]),
                              pk_hi(We1[(k0 + 8) * 256 + n], We1[(k0 + 9) * 256 + n]));
        w1n_g[i] = make_uint2(pk_hi(Wn1[k0 * 256 + n], Wn1[(k0 + 1) * 256 + n]),
                              pk_hi(Wn1[(k0 + 8) * 256 + n], Wn1[(k0 + 9) * 256 + n]));
    } else if (i < 16384) {   // W2 image: (ks2*16 + n8)*32 + lane
        int j = i - 8192;
        int lane = j & 31, n8 = (j >> 5) & 15, ks2 = j >> 9;
        int k0 = ks2 * 16 + 2 * (lane & 3), n = n8 * 8 + (lane >> 2);
        w2e_g[j] = make_uint2(pk_hi(We2[k0 * 128 + n], We2[(k0 + 1) * 128 + n]),
                              pk_hi(We2[(k0 + 8) * 128 + n], We2[(k0 + 9) * 128 + n]));
        w2n_g[j] = make_uint2(pk_hi(Wn2[k0 * 128 + n], Wn2[(k0 + 1) * 128 + n]),
                              pk_hi(Wn2[(k0 + 8) * 128 + n], Wn2[(k0 + 9) * 128 + n]));
    }
}

// ---------------- main ----------------
__device__ __forceinline__ void load_w(char* sm, const uint2* __restrict__ w1,
                                       const uint2* __restrict__ w2,
                                       const float* __restrict__ b1) {
    int tid = threadIdx.x;
    const uint4* s1 = (const uint4*)w1;
    const uint4* s2 = (const uint4*)w2;
    uint4* d1 = (uint4*)(sm + SM_W1);
    uint4* d2 = (uint4*)(sm + SM_W2);
    #pragma unroll
    for (int i = 0; i < 8; i++) {
        d1[tid + i * 512] = s1[tid + i * 512];
        d2[tid + i * 512] = s2[tid + i * 512];
    }
    if (tid < 256) ((float*)(sm + SM_B1))[tid] = b1[tid];
    __syncthreads();
}

// tile = 128 rows x 128 cols, 512 threads, warp grid 4m x 4n
__device__ __forceinline__ void do_tile(char* sm, const float* __restrict__ X,
        const float* __restrict__ Xnext,
        const float* __restrict__ gv0, const float* __restrict__ gv1,
        float* __restrict__ gs0, float* __restrict__ gs1) {
    const int tid = threadIdx.x, w = tid >> 5, lane = tid & 31;
    const int mg = w & 3, ng = w >> 2;
    const int mb = mg * 2;
    uint32_t* Xs = (uint32_t*)(sm + SM_X);
    uint32_t* Hs = (uint32_t*)(sm + SM_H);
    const uint2* W1 = (const uint2*)(sm + SM_W1);
    const uint2* W2 = (const uint2*)(sm + SM_W2);
    const float* b1s = (const float*)(sm + SM_B1);

    // prefetch next tile's X into L2 (one 128B line per thread = 64KB)
    if (Xnext) {
        const char* p = (const char*)Xnext + tid * 128;
        asm volatile("prefetch.global.L2 [%0];" :: "l"(p));
    }

    // stage X [128,128] f32 -> fp16 plane-interleaved A-fragments
    const float4* Xg = (const float4*)X;
    #pragma unroll
    for (int i = 0; i < 8; i++) {
        int idx = tid + i * 512;
        int row = idx >> 5, c4 = (idx & 31) << 2;
        float4 v = Xg[idx];
        int f = ((c4 >> 4) << 3) + (row >> 4);
        int l = ((row & 7) << 2) + ((c4 >> 1) & 3);
        int p = ((row >> 3) & 1) + (((c4 >> 3) & 1) << 1);
        Xs[(f * 32 + l) * 4 + p]     = pk_hi(v.x, v.y);
        Xs[(f * 32 + l + 1) * 4 + p] = pk_hi(v.z, v.w);
    }
    __syncthreads();

    // GEMM1: warp = 2 rt x 8 n8 (fully unrolled; ptxas pipelines LDS vs mma)
    float C[2][8][4];
    #pragma unroll
    for (int rt = 0; rt < 2; rt++)
        #pragma unroll
        for (int n = 0; n < 8; n++)
            #pragma unroll
            for (int q = 0; q < 4; q++) C[rt][n][q] = 0.f;
    const int nb = ng * 8;
    #pragma unroll
    for (int ks = 0; ks < 8; ks++) {
        uint4 a0 = *(const uint4*)(Xs + ((ks * 8 + mb) * 32 + lane) * 4);
        uint4 a1 = *(const uint4*)(Xs + ((ks * 8 + mb + 1) * 32 + lane) * 4);
        #pragma unroll
        for (int n = 0; n < 8; n++) {
            uint2 b = W1[(ks * 32 + nb + n) * 32 + lane];
            mma8(C[0][n], a0, b);
            mma8(C[1][n], a1, b);
        }
    }

    // epilogue1: bias+relu -> H fragments
    #pragma unroll
    for (int n = 0; n < 8; n++) {
        int c = (nb + n) * 8 + 2 * (lane & 3);
        float2 bb = *(const float2*)(b1s + c);
        int ks2 = (nb + n) >> 1, p = ((nb + n) & 1) * 2;
        #pragma unroll
        for (int rt = 0; rt < 2; rt++) {
            uint32_t u0 = pk_hi(fmaxf(C[rt][n][0] + bb.x, 0.f),
                                fmaxf(C[rt][n][1] + bb.y, 0.f));
            uint32_t u1 = pk_hi(fmaxf(C[rt][n][2] + bb.x, 0.f),
                                fmaxf(C[rt][n][3] + bb.y, 0.f));
            *(uint2*)(Hs + ((ks2 * 8 + mb + rt) * 32 + lane) * 4 + p) = make_uint2(u0, u1);
        }
    }
    __syncthreads();

    // GEMM2: warp = 2 rt x 4 n8 (fully unrolled)
    float C2[2][4][4];
    #pragma unroll
    for (int rt = 0; rt < 2; rt++)
        #pragma unroll
        for (int n = 0; n < 4; n++)
            #pragma unroll
            for (int q = 0; q < 4; q++) C2[rt][n][q] = 0.f;
    const int nb2 = ng * 4;
    #pragma unroll
    for (int ks2 = 0; ks2 < 16; ks2++) {
        uint4 a0 = *(const uint4*)(Hs + ((ks2 * 8 + mb) * 32 + lane) * 4);
        uint4 a1 = *(const uint4*)(Hs + ((ks2 * 8 + mb + 1) * 32 + lane) * 4);
        #pragma unroll
        for (int n = 0; n < 4; n++) {
            uint2 b = W2[(ks2 * 16 + nb2 + n) * 32 + lane];
            mma8(C2[0][n], a0, b);
            mma8(C2[1][n], a1, b);
        }
    }

    // epilogue2: +gv, relu, column sums (warp's 32-row group)
    const float* gvp = (mg >= 2) ? gv1 : gv0;
    float* gsp = (mg >= 2) ? gs1 : gs0;
    #pragma unroll
    for (int n = 0; n < 4; n++) {
        int c = (nb2 + n) * 8 + 2 * (lane & 3);
        float2 gq = *(const float2*)(gvp + c);
        float s0 = 0.f, s1 = 0.f;
        #pragma unroll
        for (int rt = 0; rt < 2; rt++) {
            s0 += fmaxf(C2[rt][n][0] + gq.x, 0.f) + fmaxf(C2[rt][n][2] + gq.x, 0.f);
            s1 += fmaxf(C2[rt][n][1] + gq.y, 0.f) + fmaxf(C2[rt][n][3] + gq.y, 0.f);
        }
        #pragma unroll
        for (int d = 4; d < 32; d <<= 1) {
            s0 += __shfl_xor_sync(0xFFFFFFFF, s0, d);
            s1 += __shfl_xor_sync(0xFFFFFFFF, s1, d);
        }
        if (lane < 4) {
            atomicAdd(gsp + c, s0);
            atomicAdd(gsp + c + 1, s1);
        }
    }
    __syncthreads();
}

__global__ __launch_bounds__(512, 1)
void gnn_main(const float* __restrict__ edges, const float* __restrict__ nodes,
              const float* __restrict__ be1, const float* __restrict__ bn1) {
    extern __shared__ char sm[];
    load_w(sm, w1e_g, w2e_g, be1);
    for (int t = blockIdx.x; t < 2048; t += 148) {
        int g = t >> 3;
        const float* nxt = (t + 148 < 2048) ? edges + (size_t)(t + 148) * 16384
                                            : ((blockIdx.x < 128) ? nodes + (size_t)blockIdx.x * 16384 : 0);
        do_tile(sm, edges + (size_t)t * 16384, nxt,
                gv_e + g * 128, gv_e + g * 128, g_esum + g * 128, g_esum + g * 128);
    }
    __syncthreads();
    load_w(sm, w1n_g, w2n_g, bn1);
    for (int t = blockIdx.x; t < 128; t += 148) {
        int g0 = t * 2;
        do_tile(sm, nodes + (size_t)t * 16384, 0,
                gv_n + g0 * 128, gv_n + g0 * 128 + 128,
                g_nsum + g0 * 128, g_nsum + g0 * 128 + 128);
    }
}

// ---------------- final: 16 blocks x 512 threads, 16 graphs/block ----------------
__global__ __launch_bounds__(512)
void final_k(const float* __restrict__ G, const float* __restrict__ A,
             const float* __restrict__ Wgn, const float* __restrict__ Wge,
             const float* __restrict__ Wgg, const float* __restrict__ bg,
             const float* __restrict__ Wh, const float* __restrict__ bh,
             const float* __restrict__ Wo, const float* __restrict__ bo,
             float* __restrict__ out) {
    __shared__ float navg[16 * 129], eavg[16 * 129], gl[16 * 66], sa[16 * 137], red[16];
    const int tid = threadIdx.x, gbase = blockIdx.x * 16;
    for (int i = tid; i < 16 * 128; i += 512) {
        int g = i >> 7, j = i & 127;
        navg[g * 129 + j] = g_nsum[(gbase + g) * 128 + j] * (1.f / 64.f);
        eavg[g * 129 + j] = g_esum[(gbase + g) * 128 + j] * (1.f / 1024.f);
    }
    for (int i = tid; i < 16 * 64; i += 512) {
        int g = i >> 6, j = i & 63;
        gl[g * 66 + j] = G[(gbase + g) * 64 + j];
    }
    if (tid < 16) red[tid] = 0.f;
    __syncthreads();
    {
        int c = tid & 127, q = tid >> 7;
        float s[4] = {0.f, 0.f, 0.f, 0.f};
        for (int j = 0; j < 128; j++) {
            float wn = __ldg(Wgn + j * 128 + c), we = __ldg(Wge + j * 128 + c);
            #pragma unroll
            for (int i = 0; i < 4; i++) {
                int g = q + 4 * i;
                s[i] += navg[g * 129 + j] * wn + eavg[g * 129 + j] * we;
            }
        }
        for (int j = 0; j < 64; j++) {
            float wg = __ldg(Wgg + j * 128 + c);
            #pragma unroll
            for (int i = 0; i < 4; i++) s[i] += gl[(q + 4 * i) * 66 + j] * wg;
        }
        float bgc = bg[c];
        #pragma unroll
        for (int i = 0; i < 4; i++) sa[(q + 4 * i) * 137 + c] = s[i] + bgc;
    }
    for (int i = tid; i < 16 * NA; i += 512) {
        int g = i >> 3, j = i & 7;
        sa[g * 137 + 128 + j] = A[(gbase + g) * NA + j];
    }
    __syncthreads();
    {
        int o = tid & 255, q = tid >> 8;
        float h[8];
        #pragma unroll
        for (int i = 0; i < 8; i++) h[i] = bh[o];
        for (int j = 0; j < 136; j++) {
            float wv = __ldg(Wh + j * 256 + o);
            #pragma unroll
            for (int i = 0; i < 8; i++) h[i] += sa[(q + 2 * i) * 137 + j] * wv;
        }
        float wo = Wo[o];
        #pragma unroll
        for (int i = 0; i < 8; i++) {
            float v = fmaxf(h[i], 0.f) * wo;
            #pragma unroll
            for (int d = 1; d < 32; d <<= 1) v += __shfl_xor_sync(0xFFFFFFFF, v, d);
            if ((tid & 31) == 0) atomicAdd(&red[q + 2 * i], v);
        }
    }
    __syncthreads();
    if (tid < 16) out[gbase + tid] = red[tid] + bo[0];
}

// ---------------- launch ----------------
extern "C" void kernel_launch(void* const* d_in, const int* in_sizes, int n_in,
                              void* d_out, int out_size) {
    (void)in_sizes; (void)n_in; (void)out_size;
    const float* nodes = (const float*)d_in[0];
    const float* edges = (const float*)d_in[1];
    const float* G     = (const float*)d_in[2];
    const float* a     = (const float*)d_in[5];
    const float* We1   = (const float*)d_in[6];
    const float* be1   = (const float*)d_in[7];
    const float* Wn1   = (const float*)d_in[8];
    const float* bn1   = (const float*)d_in[9];
    const float* We2_e = (const float*)d_in[10];
    const float* We2_g = (const float*)d_in[11];
    const float* be2   = (const float*)d_in[12];
    const float* Wn2_n = (const float*)d_in[13];
    const float* Wn2_g = (const float*)d_in[14];
    const float* bn2   = (const float*)d_in[15];
    const float* Wg_n  = (const float*)d_in[16];
    const float* Wg_e  = (const float*)d_in[17];
    const float* Wg_g  = (const float*)d_in[18];
    const float* bg    = (const float*)d_in[19];
    const float* Wh    = (const float*)d_in[20];
    const float* bh    = (const float*)d_in[21];
    const float* Wo    = (const float*)d_in[22];
    const float* bo    = (const float*)d_in[23];
    float* out = (float*)d_out;

    cudaFuncSetAttribute(gnn_main, cudaFuncAttributeMaxDynamicSharedMemorySize, SMEM_TOTAL);
    prep_all<<<256, 256>>>(G, We2_g, be2, Wn2_g, bn2, We1, Wn1, We2_e, Wn2_n);
    gnn_main<<<148, 512, SMEM_TOTAL>>>(edges, nodes, be1, bn1);
    final_k<<<16, 512>>>(G, a, Wg_n, Wg_e, Wg_g, bg, Wh, bh, Wo, bo, out);
}

// round 11
// speedup vs baseline: 1.2549x; 1.0509x over previous
#include <cuda_runtime.h>
#include <cuda_fp16.h>
#include <cstdint>

#define NA 8
#define SM_X  0           // 32768 B
#define SM_H  32768       // 65536 B
#define SM_B1 98304       // 1024 B
#define SMEM_TOTAL 99328  // <= 113.5KB -> 2 CTAs/SM

__device__ float g_esum[32768], g_nsum[32768], gv_e[32768], gv_n[32768];
__device__ uint2 w1e_g[8192], w1n_g[8192], w2e_g[8192], w2n_g[8192];

__device__ __forceinline__ uint32_t pk_hi(float a, float b) {
    __half2 h = __floats2half2_rn(a, b);
    return *(uint32_t*)&h;
}
__device__ __forceinline__ void mma8(float* c, uint4 a, uint2 b) {
    asm volatile("mma.sync.aligned.m16n8k16.row.col.f32.f16.f16.f32 "
        "{%0,%1,%2,%3}, {%4,%5,%6,%7}, {%8,%9}, {%0,%1,%2,%3};"
        : "+f"(c[0]), "+f"(c[1]), "+f"(c[2]), "+f"(c[3])
        : "r"(a.x), "r"(a.y), "r"(a.z), "r"(a.w), "r"(b.x), "r"(b.y));
}

// ---------------- prep ----------------
__global__ void prep_all(const float* __restrict__ G,
                         const float* __restrict__ We2_g, const float* __restrict__ be2,
                         const float* __restrict__ Wn2_g, const float* __restrict__ bn2,
                         const float* __restrict__ We1, const float* __restrict__ Wn1,
                         const float* __restrict__ We2, const float* __restrict__ Wn2) {
    int tid = threadIdx.x;
    if (tid < 128) {
        int g = blockIdx.x, c = tid;
        g_esum[g * 128 + c] = 0.f;
        g_nsum[g * 128 + c] = 0.f;
        float se = be2[c], sn = bn2[c];
        #pragma unroll 8
        for (int j = 0; j < 64; j++) {
            float gj = G[g * 64 + j];
            se += gj * We2_g[j * 128 + c];
            sn += gj * Wn2_g[j * 128 + c];
        }
        gv_e[g * 128 + c] = se;
        gv_n[g * 128 + c] = sn;
    }
    int i = blockIdx.x * 256 + tid;
    if (i < 8192) {   // W1 image: (ks*32 + n8)*32 + lane
        int lane = i & 31, n8 = (i >> 5) & 31, ks = i >> 10;
        int k0 = ks * 16 + 2 * (lane & 3), n = n8 * 8 + (lane >> 2);
        w1e_g[i] = make_uint2(pk_hi(We1[k0 * 256 + n], We1[(k0 + 1) * 256 + n]),
                              pk_hi(We1[(k0 + 8) * 256 + n], We1[(k0 + 9) * 256 + n]));
        w1n_g[i] = make_uint2(pk_hi(Wn1[k0 * 256 + n], Wn1[(k0 + 1) * 256 + n]),
                              pk_hi(Wn1[(k0 + 8) * 256 + n], Wn1[(k0 + 9) * 256 + n]));
    } else if (i < 16384) {   // W2 image: (ks2*16 + n8)*32 + lane
        int j = i - 8192;
        int lane = j & 31, n8 = (j >> 5) & 15, ks2 = j >> 9;
        int k0 = ks2 * 16 + 2 * (lane & 3), n = n8 * 8 + (lane >> 2);
        w2e_g[j] = make_uint2(pk_hi(We2[k0 * 128 + n], We2[(k0 + 1) * 128 + n]),
                              pk_hi(We2[(k0 + 8) * 128 + n], We2[(k0 + 9) * 128 + n]));
        w2n_g[j] = make_uint2(pk_hi(Wn2[k0 * 128 + n], Wn2[(k0 + 1) * 128 + n]),
                              pk_hi(Wn2[(k0 + 8) * 128 + n], Wn2[(k0 + 9) * 128 + n]));
    }
}

// ---------------- main: tile 128x128, 256 threads (8 warps), 2 CTAs/SM --------
// GEMM1: two n-halves; per half warp grid 4m x 2n (2 m-tiles x 8 n8 per warp).
// GEMM2: single pass, warp grid 4m x 2n (2 m-tiles x 8 n8 per warp).
__device__ __forceinline__ void do_tile(char* sm, const float* __restrict__ X,
        const uint2* __restrict__ w1, const uint2* __restrict__ w2,
        const float* __restrict__ gv0, const float* __restrict__ gv1,
        float* __restrict__ gs0, float* __restrict__ gs1) {
    const int tid = threadIdx.x, w = tid >> 5, lane = tid & 31;
    const int mg = w & 3, ng = w >> 2;     // 4m x 2n warp grid
    const int mb = mg * 2;
    uint32_t* Xs = (uint32_t*)(sm + SM_X);
    uint32_t* Hs = (uint32_t*)(sm + SM_H);
    const float* b1s = (const float*)(sm + SM_B1);

    // stage X [128,128] f32 -> fp16 plane-interleaved A-fragments
    const float4* Xg = (const float4*)X;
    #pragma unroll
    for (int i = 0; i < 16; i++) {
        int idx = tid + i * 256;
        int row = idx >> 5, c4 = (idx & 31) << 2;
        float4 v = Xg[idx];
        int f = ((c4 >> 4) << 3) + (row >> 4);
        int l = ((row & 7) << 2) + ((c4 >> 1) & 3);
        int p = ((row >> 3) & 1) + (((c4 >> 3) & 1) << 1);
        Xs[(f * 32 + l) * 4 + p]     = pk_hi(v.x, v.y);
        Xs[(f * 32 + l + 1) * 4 + p] = pk_hi(v.z, v.w);
    }
    __syncthreads();

    // GEMM1 in two n-halves (keeps accumulators at 64 regs)
    #pragma unroll
    for (int h = 0; h < 2; h++) {
        const int nb = h * 16 + ng * 8;
        float C[2][8][4];
        #pragma unroll
        for (int rt = 0; rt < 2; rt++)
            #pragma unroll
            for (int n = 0; n < 8; n++)
                #pragma unroll
                for (int q = 0; q < 4; q++) C[rt][n][q] = 0.f;
        #pragma unroll
        for (int ks = 0; ks < 8; ks++) {
            uint4 a0 = *(const uint4*)(Xs + ((ks * 8 + mb) * 32 + lane) * 4);
            uint4 a1 = *(const uint4*)(Xs + ((ks * 8 + mb + 1) * 32 + lane) * 4);
            #pragma unroll
            for (int n = 0; n < 8; n++) {
                uint2 b = __ldg(&w1[(ks * 32 + nb + n) * 32 + lane]);
                mma8(C[0][n], a0, b);
                mma8(C[1][n], a1, b);
            }
        }
        // epilogue1: bias+relu -> H fragments
        #pragma unroll
        for (int n = 0; n < 8; n++) {
            int c = (nb + n) * 8 + 2 * (lane & 3);
            float2 bb = *(const float2*)(b1s + c);
            int ks2 = (nb + n) >> 1, p = ((nb + n) & 1) * 2;
            #pragma unroll
            for (int rt = 0; rt < 2; rt++) {
                uint32_t u0 = pk_hi(fmaxf(C[rt][n][0] + bb.x, 0.f),
                                    fmaxf(C[rt][n][1] + bb.y, 0.f));
                uint32_t u1 = pk_hi(fmaxf(C[rt][n][2] + bb.x, 0.f),
                                    fmaxf(C[rt][n][3] + bb.y, 0.f));
                *(uint2*)(Hs + ((ks2 * 8 + mb + rt) * 32 + lane) * 4 + p) = make_uint2(u0, u1);
            }
        }
    }
    __syncthreads();

    // GEMM2: warp = 2 m-tiles x 8 n8
    float C2[2][8][4];
    #pragma unroll
    for (int rt = 0; rt < 2; rt++)
        #pragma unroll
        for (int n = 0; n < 8; n++)
            #pragma unroll
            for (int q = 0; q < 4; q++) C2[rt][n][q] = 0.f;
    const int nb2 = ng * 8;
    #pragma unroll
    for (int ks2 = 0; ks2 < 16; ks2++) {
        uint4 a0 = *(const uint4*)(Hs + ((ks2 * 8 + mb) * 32 + lane) * 4);
        uint4 a1 = *(const uint4*)(Hs + ((ks2 * 8 + mb + 1) * 32 + lane) * 4);
        #pragma unroll
        for (int n = 0; n < 8; n++) {
            uint2 b = __ldg(&w2[(ks2 * 16 + nb2 + n) * 32 + lane]);
            mma8(C2[0][n], a0, b);
            mma8(C2[1][n], a1, b);
        }
    }

    // epilogue2: +gv, relu, column sums (warp rows [mg*32, mg*32+32))
    const float* gvp = (mg >= 2) ? gv1 : gv0;
    float* gsp = (mg >= 2) ? gs1 : gs0;
    #pragma unroll
    for (int n = 0; n < 8; n++) {
        int c = (nb2 + n) * 8 + 2 * (lane & 3);
        float2 gq = *(const float2*)(gvp + c);
        float s0 = 0.f, s1 = 0.f;
        #pragma unroll
        for (int rt = 0; rt < 2; rt++) {
            s0 += fmaxf(C2[rt][n][0] + gq.x, 0.f) + fmaxf(C2[rt][n][2] + gq.x, 0.f);
            s1 += fmaxf(C2[rt][n][1] + gq.y, 0.f) + fmaxf(C2[rt][n][3] + gq.y, 0.f);
        }
        #pragma unroll
        for (int d = 4; d < 32; d <<= 1) {
            s0 += __shfl_xor_sync(0xFFFFFFFF, s0, d);
            s1 += __shfl_xor_sync(0xFFFFFFFF, s1, d);
        }
        if (lane < 4) {
            atomicAdd(gsp + c, s0);
            atomicAdd(gsp + c + 1, s1);
        }
    }
    __syncthreads();
}

__global__ __launch_bounds__(256, 2)
void gnn_main(const float* __restrict__ edges, const float* __restrict__ nodes,
              const float* __restrict__ be1, const float* __restrict__ bn1) {
    extern __shared__ char sm[];
    const int tid = threadIdx.x;
    // edges phase
    if (tid < 256) ((float*)(sm + SM_B1))[tid] = be1[tid];
    __syncthreads();
    for (int t = blockIdx.x; t < 2048; t += 296) {
        int g = t >> 3;
        do_tile(sm, edges + (size_t)t * 16384, w1e_g, w2e_g,
                gv_e + g * 128, gv_e + g * 128, g_esum + g * 128, g_esum + g * 128);
    }
    __syncthreads();
    // nodes phase
    if (tid < 256) ((float*)(sm + SM_B1))[tid] = bn1[tid];
    __syncthreads();
    for (int t = blockIdx.x; t < 128; t += 296) {
        int g0 = t * 2;
        do_tile(sm, nodes + (size_t)t * 16384, w1n_g, w2n_g,
                gv_n + g0 * 128, gv_n + g0 * 128 + 128,
                g_nsum + g0 * 128, g_nsum + g0 * 128 + 128);
    }
}

// ---------------- final: 16 blocks x 512 threads, 16 graphs/block ----------------
__global__ __launch_bounds__(512)
void final_k(const float* __restrict__ G, const float* __restrict__ A,
             const float* __restrict__ Wgn, const float* __restrict__ Wge,
             const float* __restrict__ Wgg, const float* __restrict__ bg,
             const float* __restrict__ Wh, const float* __restrict__ bh,
             const float* __restrict__ Wo, const float* __restrict__ bo,
             float* __restrict__ out) {
    __shared__ float navg[16 * 129], eavg[16 * 129], gl[16 * 66], sa[16 * 137], red[16];
    const int tid = threadIdx.x, gbase = blockIdx.x * 16;
    for (int i = tid; i < 16 * 128; i += 512) {
        int g = i >> 7, j = i & 127;
        navg[g * 129 + j] = g_nsum[(gbase + g) * 128 + j] * (1.f / 64.f);
        eavg[g * 129 + j] = g_esum[(gbase + g) * 128 + j] * (1.f / 1024.f);
    }
    for (int i = tid; i < 16 * 64; i += 512) {
        int g = i >> 6, j = i & 63;
        gl[g * 66 + j] = G[(gbase + g) * 64 + j];
    }
    if (tid < 16) red[tid] = 0.f;
    __syncthreads();
    {
        int c = tid & 127, q = tid >> 7;
        float s[4] = {0.f, 0.f, 0.f, 0.f};
        for (int j = 0; j < 128; j++) {
            float wn = __ldg(Wgn + j * 128 + c), we = __ldg(Wge + j * 128 + c);
            #pragma unroll
            for (int i = 0; i < 4; i++) {
                int g = q + 4 * i;
                s[i] += navg[g * 129 + j] * wn + eavg[g * 129 + j] * we;
            }
        }
        for (int j = 0; j < 64; j++) {
            float wg = __ldg(Wgg + j * 128 + c);
            #pragma unroll
            for (int i = 0; i < 4; i++) s[i] += gl[(q + 4 * i) * 66 + j] * wg;
        }
        float bgc = bg[c];
        #pragma unroll
        for (int i = 0; i < 4; i++) sa[(q + 4 * i) * 137 + c] = s[i] + bgc;
    }
    for (int i = tid; i < 16 * NA; i += 512) {
        int g = i >> 3, j = i & 7;
        sa[g * 137 + 128 + j] = A[(gbase + g) * NA + j];
    }
    __syncthreads();
    {
        int o = tid & 255, q = tid >> 8;
        float h[8];
        #pragma unroll
        for (int i = 0; i < 8; i++) h[i] = bh[o];
        for (int j = 0; j < 136; j++) {
            float wv = __ldg(Wh + j * 256 + o);
            #pragma unroll
            for (int i = 0; i < 8; i++) h[i] += sa[(q + 2 * i) * 137 + j] * wv;
        }
        float wo = Wo[o];
        #pragma unroll
        for (int i = 0; i < 8; i++) {
            float v = fmaxf(h[i], 0.f) * wo;
            #pragma unroll
            for (int d = 1; d < 32; d <<= 1) v += __shfl_xor_sync(0xFFFFFFFF, v, d);
            if ((tid & 31) == 0) atomicAdd(&red[q + 2 * i], v);
        }
    }
    __syncthreads();
    if (tid < 16) out[gbase + tid] = red[tid] + bo[0];
}

// ---------------- launch ----------------
extern "C" void kernel_launch(void* const* d_in, const int* in_sizes, int n_in,
                              void* d_out, int out_size) {
    (void)in_sizes; (void)n_in; (void)out_size;
    const float* nodes = (const float*)d_in[0];
    const float* edges = (const float*)d_in[1];
    const float* G     = (const float*)d_in[2];
    const float* a     = (const float*)d_in[5];
    const float* We1   = (const float*)d_in[6];
    const float* be1   = (const float*)d_in[7];
    const float* Wn1   = (const float*)d_in[8];
    const float* bn1   = (const float*)d_in[9];
    const float* We2_e = (const float*)d_in[10];
    const float* We2_g = (const float*)d_in[11];
    const float* be2   = (const float*)d_in[12];
    const float* Wn2_n = (const float*)d_in[13];
    const float* Wn2_g = (const float*)d_in[14];
    const float* bn2   = (const float*)d_in[15];
    const float* Wg_n  = (const float*)d_in[16];
    const float* Wg_e  = (const float*)d_in[17];
    const float* Wg_g  = (const float*)d_in[18];
    const float* bg    = (const float*)d_in[19];
    const float* Wh    = (const float*)d_in[20];
    const float* bh    = (const float*)d_in[21];
    const float* Wo    = (const float*)d_in[22];
    const float* bo    = (const float*)d_in[23];
    float* out = (float*)d_out;

    cudaFuncSetAttribute(gnn_main, cudaFuncAttributeMaxDynamicSharedMemorySize, SMEM_TOTAL);
    prep_all<<<256, 256>>>(G, We2_g, be2, Wn2_g, bn2, We1, Wn1, We2_e, Wn2_n);
    gnn_main<<<296, 256, SMEM_TOTAL>>>(edges, nodes, be1, bn1);
    final_k<<<16, 512>>>(G, a, Wg_n, Wg_e, Wg_g, bg, Wh, bh, Wo, bo, out);
}